// round 4
// baseline (speedup 1.0000x reference)
#include <cuda_runtime.h>

#define NB 8
#define NT 2048
#define NC 1024
#define NH 64
#define BT (NB*NT)
#define NPAIR 80        // sum_i ceil((i+1)/8), i=0..31
#define MAXCH 4

// scratch (allocation-free rule -> __device__ globals)
__device__ unsigned g_q[BT*NH];          // tf32 bits
__device__ unsigned g_k[BT*NH];
__device__ unsigned g_v[BT*NH];
__device__ unsigned g_wc[192*NC];        // pre-converted W
__device__ float    g_po[MAXCH][BT*NH];  // split-K partial numerators
__device__ float    g_prs[MAXCH][BT];    // split-K partial row sums

__device__ __forceinline__ unsigned f2tf32(float f) {
    unsigned u;
    asm("cvt.rna.tf32.f32 %0, %1;" : "=r"(u) : "f"(f));
    return u;
}

__device__ __forceinline__ void mma_tf32(float* d, const unsigned* a, const unsigned* b) {
    asm volatile(
        "mma.sync.aligned.m16n8k8.row.col.f32.tf32.tf32.f32 "
        "{%0,%1,%2,%3}, {%4,%5,%6,%7}, {%8,%9}, {%0,%1,%2,%3};\n"
        : "+f"(d[0]), "+f"(d[1]), "+f"(d[2]), "+f"(d[3])
        : "r"(a[0]), "r"(a[1]), "r"(a[2]), "r"(a[3]), "r"(b[0]), "r"(b[1]));
}

__device__ __forceinline__ void cp16(unsigned saddr, const void* gaddr) {
    asm volatile("cp.async.cg.shared.global [%0], [%1], 16;"
                 :: "r"(saddr), "l"(gaddr));
}
#define CP_COMMIT() asm volatile("cp.async.commit_group;")
#define CP_WAIT0()  asm volatile("cp.async.wait_group 0;")

// ---------------------------------------------------------------------------
// Pre-convert weights to tf32 ONCE.
// ---------------------------------------------------------------------------
__global__ __launch_bounds__(256) void wcvt_kernel(const float* __restrict__ Wq,
                                                   const float* __restrict__ Wk,
                                                   const float* __restrict__ Wv) {
    int idx = blockIdx.x * 256 + threadIdx.x;
    int m = idx >> 16;
    const float* W = (m == 0) ? Wq : (m == 1) ? Wk : Wv;
    g_wc[idx] = f2tf32(W[idx & 65535]);
}

// ---------------------------------------------------------------------------
// Kernel 1: fused QKV projection (unchanged from round 3 — proven).
// ---------------------------------------------------------------------------
__global__ __launch_bounds__(256, 2) void proj_kernel(const float* __restrict__ x) {
    extern __shared__ unsigned psm[];
    unsigned* xs = psm;                  // [2][64][36]
    unsigned* ws = psm + 2 * 64 * 36;    // [2][192][36]

    int t = threadIdx.x, lane = t & 31, warp = t >> 5;
    int wm = warp >> 2, wn = warp & 3;
    int g = lane >> 2, tg = lane & 3;
    int row0 = blockIdx.x * 64;

    float d[2][6][4];
    #pragma unroll
    for (int mt = 0; mt < 2; mt++)
        #pragma unroll
        for (int nt = 0; nt < 6; nt++)
            #pragma unroll
            for (int c = 0; c < 4; c++) d[mt][nt][c] = 0.f;

    float4 rx[2];
    uint4  rw[6];

    #pragma unroll
    for (int it2 = 0; it2 < 2; it2++) {
        int e = t + it2 * 256, r = e >> 3, c4 = (e & 7) * 4;
        rx[it2] = *(const float4*)&x[(size_t)(row0 + r) * NC + c4];
    }
    #pragma unroll
    for (int it2 = 0; it2 < 6; it2++) {
        int e = t + it2 * 256, r = e >> 3, c4 = (e & 7) * 4;
        rw[it2] = *(const uint4*)&g_wc[(size_t)r * NC + c4];
    }
    #pragma unroll
    for (int it2 = 0; it2 < 2; it2++) {
        int e = t + it2 * 256, r = e >> 3, c4 = (e & 7) * 4;
        uint4 v = make_uint4(f2tf32(rx[it2].x), f2tf32(rx[it2].y),
                             f2tf32(rx[it2].z), f2tf32(rx[it2].w));
        *(uint4*)&xs[r * 36 + c4] = v;
    }
    #pragma unroll
    for (int it2 = 0; it2 < 6; it2++) {
        int e = t + it2 * 256, r = e >> 3, c4 = (e & 7) * 4;
        *(uint4*)&ws[r * 36 + c4] = rw[it2];
    }
    __syncthreads();

    int buf = 0;
    for (int it = 0; it < 32; it++) {
        if (it < 31) {
            int k0 = (it + 1) * 32;
            #pragma unroll
            for (int it2 = 0; it2 < 2; it2++) {
                int e = t + it2 * 256, r = e >> 3, c4 = (e & 7) * 4;
                rx[it2] = *(const float4*)&x[(size_t)(row0 + r) * NC + k0 + c4];
            }
            #pragma unroll
            for (int it2 = 0; it2 < 6; it2++) {
                int e = t + it2 * 256, r = e >> 3, c4 = (e & 7) * 4;
                rw[it2] = *(const uint4*)&g_wc[(size_t)r * NC + k0 + c4];
            }
        }

        const unsigned* xb = xs + buf * (64 * 36);
        const unsigned* wb = ws + buf * (192 * 36);
        #pragma unroll
        for (int ks = 0; ks < 4; ks++) {
            int kb = ks * 8;
            unsigned a[2][4], b[6][2];
            #pragma unroll
            for (int mt = 0; mt < 2; mt++) {
                int r = wm * 32 + mt * 16 + g;
                a[mt][0] = xb[r * 36 + kb + tg];
                a[mt][1] = xb[(r + 8) * 36 + kb + tg];
                a[mt][2] = xb[r * 36 + kb + tg + 4];
                a[mt][3] = xb[(r + 8) * 36 + kb + tg + 4];
            }
            #pragma unroll
            for (int nt = 0; nt < 6; nt++) {
                int c = wn * 48 + nt * 8 + g;
                b[nt][0] = wb[c * 36 + kb + tg];
                b[nt][1] = wb[c * 36 + kb + tg + 4];
            }
            #pragma unroll
            for (int mt = 0; mt < 2; mt++)
                #pragma unroll
                for (int nt = 0; nt < 6; nt++)
                    mma_tf32(d[mt][nt], a[mt], b[nt]);
        }

        if (it < 31) {
            unsigned* xo = xs + (buf ^ 1) * (64 * 36);
            unsigned* wo = ws + (buf ^ 1) * (192 * 36);
            #pragma unroll
            for (int it2 = 0; it2 < 2; it2++) {
                int e = t + it2 * 256, r = e >> 3, c4 = (e & 7) * 4;
                uint4 v = make_uint4(f2tf32(rx[it2].x), f2tf32(rx[it2].y),
                                     f2tf32(rx[it2].z), f2tf32(rx[it2].w));
                *(uint4*)&xo[r * 36 + c4] = v;
            }
            #pragma unroll
            for (int it2 = 0; it2 < 6; it2++) {
                int e = t + it2 * 256, r = e >> 3, c4 = (e & 7) * 4;
                *(uint4*)&wo[r * 36 + c4] = rw[it2];
            }
        }
        __syncthreads();
        buf ^= 1;
    }

    #pragma unroll
    for (int mt = 0; mt < 2; mt++) {
        int r = row0 + wm * 32 + mt * 16 + g;
        #pragma unroll
        for (int nt = 0; nt < 6; nt++) {
            int c = wn * 48 + nt * 8 + tg * 2;
            int m = c >> 6, col = c & 63;
            unsigned* O = (m == 0) ? g_q : (m == 1) ? g_k : g_v;
            uint2 v0 = make_uint2(f2tf32(d[mt][nt][0]), f2tf32(d[mt][nt][1]));
            uint2 v1 = make_uint2(f2tf32(d[mt][nt][2]), f2tf32(d[mt][nt][3]));
            *(uint2*)&O[(size_t)r * NH + col]       = v0;
            *(uint2*)&O[(size_t)(r + 8) * NH + col] = v1;
        }
    }
}

// ---------------------------------------------------------------------------
// Kernel 2: causal attention, split-K, cp.async double-buffered K/V.
// 4 warps, 64-query tile; Q fragments register-resident; P reuses K[buf]
// (prefetch writes K[buf^1] -> no conflict). nch==1 tiles write out directly.
// ---------------------------------------------------------------------------
__global__ __launch_bounds__(128, 3) void attn_kernel(float* __restrict__ out) {
    extern __shared__ unsigned sm[];
    // layout: K0[64x68], K1[64x68], V0[64x72], V1[64x72]
    unsigned* Ksm = sm;
    unsigned* Vsm = sm + 2 * 64 * 68;
    unsigned smem_u32 = (unsigned)__cvta_generic_to_shared(sm);
    unsigned ksm_u32 = smem_u32;
    unsigned vsm_u32 = smem_u32 + 2 * 64 * 68 * 4;

    int t = threadIdx.x, lane = t & 31, w = t >> 5;
    int g = lane >> 2, tg = lane & 3;
    int b = blockIdx.y;

    // decode (q-tile i, chunk); heavy pairs first
    int p = NPAIR - 1 - blockIdx.x;
    int i = 0, nch = 1;
    while (p >= nch) { p -= nch; i++; nch = (i >> 3) + 1; }
    int chunk = p;
    int q0 = i * 64;
    int kt0 = chunk * 8;
    int kt1 = min(kt0 + 8, i + 1);
    int ntiles = kt1 - kt0;

    // prologue: start K/V(kt0) into buffer 0
    {
        const unsigned* kg = g_k + (size_t)(b * NT + kt0 * 64) * NH;
        const unsigned* vg = g_v + (size_t)(b * NT + kt0 * 64) * NH;
        #pragma unroll
        for (int it = 0; it < 8; it++) {
            int e = t + it * 128, r = e >> 4, c4 = (e & 15) * 4;
            cp16(ksm_u32 + (r * 68 + c4) * 4, kg + r * NH + c4);
            cp16(vsm_u32 + (r * 72 + c4) * 4, vg + r * NH + c4);
        }
        CP_COMMIT();
    }

    // Q fragments (register-resident, one-time scattered LDG)
    unsigned qa[8][4];
    {
        const unsigned* qg = g_q + (size_t)(b * NT + q0) * NH;
        int r = w * 16 + g;
        #pragma unroll
        for (int ks = 0; ks < 8; ks++) {
            int kb = ks * 8;
            qa[ks][0] = qg[r * NH + kb + tg];
            qa[ks][1] = qg[(r + 8) * NH + kb + tg];
            qa[ks][2] = qg[r * NH + kb + tg + 4];
            qa[ks][3] = qg[(r + 8) * NH + kb + tg + 4];
        }
    }

    float o[8][4];
    #pragma unroll
    for (int nt = 0; nt < 8; nt++)
        #pragma unroll
        for (int c = 0; c < 4; c++) o[nt][c] = 0.f;
    float rs0 = 0.f, rs1 = 0.f;

    for (int n = 0; n < ntiles; n++) {
        int kt = kt0 + n;
        int s0 = kt * 64;
        int buf = n & 1;
        unsigned* Kb = Ksm + buf * (64 * 68);
        unsigned* Vb = Vsm + buf * (64 * 72);

        CP_WAIT0();        // tile n arrived (only group outstanding)
        __syncthreads();   // cross-thread visibility + buf^1 consumers done

        if (n + 1 < ntiles) {   // prefetch tile n+1 into buf^1
            const unsigned* kg = g_k + (size_t)(b * NT + s0 + 64) * NH;
            const unsigned* vg = g_v + (size_t)(b * NT + s0 + 64) * NH;
            unsigned kd = ksm_u32 + (buf ^ 1) * (64 * 68 * 4);
            unsigned vd = vsm_u32 + (buf ^ 1) * (64 * 72 * 4);
            #pragma unroll
            for (int it = 0; it < 8; it++) {
                int e = t + it * 128, r = e >> 4, c4 = (e & 15) * 4;
                cp16(kd + (r * 68 + c4) * 4, kg + r * NH + c4);
                cp16(vd + (r * 72 + c4) * 4, vg + r * NH + c4);
            }
            CP_COMMIT();
        }

        bool diag = (kt == i);
        int lim = diag ? (w * 16 + 15) : 1000000;   // mma-skip bound

        // S = Q K^T
        float s[8][4];
        #pragma unroll
        for (int nt = 0; nt < 8; nt++)
            #pragma unroll
            for (int c = 0; c < 4; c++) s[nt][c] = 0.f;
        #pragma unroll
        for (int ks = 0; ks < 8; ks++) {
            int kb = ks * 8;
            #pragma unroll
            for (int nt = 0; nt < 8; nt++) {
                if (nt * 8 <= lim) {
                    unsigned bf[2];
                    int c = nt * 8 + g;
                    bf[0] = Kb[c * 68 + kb + tg];
                    bf[1] = Kb[c * 68 + kb + tg + 4];
                    mma_tf32(s[nt], qa[ks], bf);
                }
            }
        }

        // exp + causal mask + row sums
        int qi0 = q0 + w * 16 + g;
        float p0 = 0.f, p1 = 0.f;
        #pragma unroll
        for (int nt = 0; nt < 8; nt++) {
            int c0 = s0 + nt * 8 + tg * 2;
            float e0 = __expf(s[nt][0] * 0.125f);
            float e1 = __expf(s[nt][1] * 0.125f);
            float e2 = __expf(s[nt][2] * 0.125f);
            float e3 = __expf(s[nt][3] * 0.125f);
            if (diag) {
                if (c0 > qi0)         e0 = 0.f;
                if (c0 + 1 > qi0)     e1 = 0.f;
                if (c0 > qi0 + 8)     e2 = 0.f;
                if (c0 + 1 > qi0 + 8) e3 = 0.f;
            }
            s[nt][0] = e0; s[nt][1] = e1; s[nt][2] = e2; s[nt][3] = e3;
            p0 += e0 + e1; p1 += e2 + e3;
        }
        p0 += __shfl_xor_sync(0xffffffffu, p0, 1);
        p0 += __shfl_xor_sync(0xffffffffu, p0, 2);
        p1 += __shfl_xor_sync(0xffffffffu, p1, 1);
        p1 += __shfl_xor_sync(0xffffffffu, p1, 2);
        rs0 += p0; rs1 += p1;

        __syncthreads();   // all warps done reading Kb as K -> safe to write P
        #pragma unroll
        for (int nt = 0; nt < 8; nt++) {
            int r = w * 16 + g, c = nt * 8 + tg * 2;
            Kb[r * 68 + c]           = f2tf32(s[nt][0]);
            Kb[r * 68 + c + 1]       = f2tf32(s[nt][1]);
            Kb[(r + 8) * 68 + c]     = f2tf32(s[nt][2]);
            Kb[(r + 8) * 68 + c + 1] = f2tf32(s[nt][3]);
        }
        __syncwarp();      // P rows are warp-local

        // O += P V
        #pragma unroll
        for (int ks = 0; ks < 8; ks++) {
            if (ks * 8 <= lim) {       // zero-P blocks skipped on diag tile
                int kb = ks * 8, r = w * 16 + g;
                unsigned pa[4];
                pa[0] = Kb[r * 68 + kb + tg];
                pa[1] = Kb[(r + 8) * 68 + kb + tg];
                pa[2] = Kb[r * 68 + kb + tg + 4];
                pa[3] = Kb[(r + 8) * 68 + kb + tg + 4];
                #pragma unroll
                for (int nt = 0; nt < 8; nt++) {
                    unsigned bf[2];
                    int nn = nt * 8 + g;
                    bf[0] = Vb[(kb + tg) * 72 + nn];
                    bf[1] = Vb[(kb + tg + 4) * 72 + nn];
                    mma_tf32(o[nt], pa, bf);
                }
            }
        }
    }

    int rbase = b * NT + q0 + w * 16 + g;
    if (nch == 1) {
        // single chunk: normalize and write final output directly
        float inv0 = 1.f / rs0, inv1 = 1.f / rs1;
        #pragma unroll
        for (int nt = 0; nt < 8; nt++) {
            int c = nt * 8 + tg * 2;
            *(float2*)&out[(size_t)rbase * NH + c] =
                make_float2(o[nt][0] * inv0, o[nt][1] * inv0);
            *(float2*)&out[(size_t)(rbase + 8) * NH + c] =
                make_float2(o[nt][2] * inv1, o[nt][3] * inv1);
        }
    } else {
        float* po = g_po[chunk];
        #pragma unroll
        for (int nt = 0; nt < 8; nt++) {
            int c = nt * 8 + tg * 2;
            *(float2*)&po[(size_t)rbase * NH + c]       = make_float2(o[nt][0], o[nt][1]);
            *(float2*)&po[(size_t)(rbase + 8) * NH + c] = make_float2(o[nt][2], o[nt][3]);
        }
        if (tg == 0) {
            g_prs[chunk][rbase]     = rs0;
            g_prs[chunk][rbase + 8] = rs1;
        }
    }
}

// ---------------------------------------------------------------------------
// Kernel 3: combine split-K partials (tail rows only: q-tile i >= 8), float4.
// ---------------------------------------------------------------------------
__global__ __launch_bounds__(256) void reduce_kernel(float* __restrict__ out) {
    int f4 = blockIdx.x * 256 + threadIdx.x;   // 0..196607
    int rr = f4 >> 4;                          // tail-row id, 0..12287
    int bb = rr / 1536;
    int rl = rr - bb * 1536;
    int r  = bb * NT + 512 + rl;
    int i  = (512 + rl) >> 6;
    int nch = (i >> 3) + 1;                    // 2..4
    int c4 = (f4 & 15) * 4;
    size_t off = (size_t)r * NH + c4;
    float4 num = *(const float4*)&g_po[0][off];
    float  den = g_prs[0][r];
    for (int c = 1; c < nch; c++) {
        float4 q = *(const float4*)&g_po[c][off];
        num.x += q.x; num.y += q.y; num.z += q.z; num.w += q.w;
        den += g_prs[c][r];
    }
    float inv = 1.f / den;
    *(float4*)&out[off] = make_float4(num.x * inv, num.y * inv,
                                      num.z * inv, num.w * inv);
}

extern "C" void kernel_launch(void* const* d_in, const int* in_sizes, int n_in,
                              void* d_out, int out_size) {
    const float* x  = (const float*)d_in[0];
    const float* Wk = (const float*)d_in[1];
    const float* Wq = (const float*)d_in[2];
    const float* Wv = (const float*)d_in[3];
    float* out = (float*)d_out;

    const int proj_smem = (2 * 64 * 36 + 2 * 192 * 36) * 4;   // 73728 B
    const int attn_smem = (2 * 64 * 68 + 2 * 64 * 72) * 4;    // 71680 B
    (void)cudaFuncSetAttribute(proj_kernel,
                               cudaFuncAttributeMaxDynamicSharedMemorySize,
                               proj_smem);
    (void)cudaFuncSetAttribute(attn_kernel,
                               cudaFuncAttributeMaxDynamicSharedMemorySize,
                               attn_smem);

    wcvt_kernel<<<192 * NC / 256, 256>>>(Wq, Wk, Wv);
    proj_kernel<<<BT / 64, 256, proj_smem>>>(x);
    attn_kernel<<<dim3(NPAIR, NB), 128, attn_smem>>>(out);
    reduce_kernel<<<768, 256>>>(out);
}

// round 5
// speedup vs baseline: 1.1353x; 1.1353x over previous
#include <cuda_runtime.h>

#define NB 8
#define NT 2048
#define NC 1024
#define NH 64
#define BT (NB*NT)
#define NPAIR 80        // sum_i ceil((i+1)/8), i=0..31
#define MAXCH 4

// scratch (allocation-free rule -> __device__ globals)
__device__ unsigned g_q[BT*NH];          // tf32 bits
__device__ unsigned g_k[BT*NH];
__device__ unsigned g_v[BT*NH];
__device__ unsigned g_wc[192*NC];        // pre-converted W
__device__ float    g_po[MAXCH][BT*NH];  // split-K partial numerators
__device__ float    g_prs[MAXCH][BT];    // split-K partial row sums

__device__ __forceinline__ unsigned f2tf32(float f) {
    unsigned u;
    asm("cvt.rna.tf32.f32 %0, %1;" : "=r"(u) : "f"(f));
    return u;
}

__device__ __forceinline__ void mma_tf32(float* d, const unsigned* a, const unsigned* b) {
    asm volatile(
        "mma.sync.aligned.m16n8k8.row.col.f32.tf32.tf32.f32 "
        "{%0,%1,%2,%3}, {%4,%5,%6,%7}, {%8,%9}, {%0,%1,%2,%3};\n"
        : "+f"(d[0]), "+f"(d[1]), "+f"(d[2]), "+f"(d[3])
        : "r"(a[0]), "r"(a[1]), "r"(a[2]), "r"(a[3]), "r"(b[0]), "r"(b[1]));
}

__device__ __forceinline__ void cp16(unsigned saddr, const void* gaddr) {
    asm volatile("cp.async.cg.shared.global [%0], [%1], 16;"
                 :: "r"(saddr), "l"(gaddr));
}
#define CP_COMMIT() asm volatile("cp.async.commit_group;")
#define CP_WAIT0()  asm volatile("cp.async.wait_group 0;")

// ---------------------------------------------------------------------------
// Pre-convert weights to tf32 ONCE.
// ---------------------------------------------------------------------------
__global__ __launch_bounds__(256) void wcvt_kernel(const float* __restrict__ Wq,
                                                   const float* __restrict__ Wk,
                                                   const float* __restrict__ Wv) {
    int idx = blockIdx.x * 256 + threadIdx.x;
    int m = idx >> 16;
    const float* W = (m == 0) ? Wq : (m == 1) ? Wk : Wv;
    g_wc[idx] = f2tf32(W[idx & 65535]);
}

// ---------------------------------------------------------------------------
// Kernel 1: fused QKV projection (unchanged — proven).
// ---------------------------------------------------------------------------
__global__ __launch_bounds__(256, 2) void proj_kernel(const float* __restrict__ x) {
    extern __shared__ unsigned psm[];
    unsigned* xs = psm;                  // [2][64][36]
    unsigned* ws = psm + 2 * 64 * 36;    // [2][192][36]

    int t = threadIdx.x, lane = t & 31, warp = t >> 5;
    int wm = warp >> 2, wn = warp & 3;
    int g = lane >> 2, tg = lane & 3;
    int row0 = blockIdx.x * 64;

    float d[2][6][4];
    #pragma unroll
    for (int mt = 0; mt < 2; mt++)
        #pragma unroll
        for (int nt = 0; nt < 6; nt++)
            #pragma unroll
            for (int c = 0; c < 4; c++) d[mt][nt][c] = 0.f;

    float4 rx[2];
    uint4  rw[6];

    #pragma unroll
    for (int it2 = 0; it2 < 2; it2++) {
        int e = t + it2 * 256, r = e >> 3, c4 = (e & 7) * 4;
        rx[it2] = *(const float4*)&x[(size_t)(row0 + r) * NC + c4];
    }
    #pragma unroll
    for (int it2 = 0; it2 < 6; it2++) {
        int e = t + it2 * 256, r = e >> 3, c4 = (e & 7) * 4;
        rw[it2] = *(const uint4*)&g_wc[(size_t)r * NC + c4];
    }
    #pragma unroll
    for (int it2 = 0; it2 < 2; it2++) {
        int e = t + it2 * 256, r = e >> 3, c4 = (e & 7) * 4;
        uint4 v = make_uint4(f2tf32(rx[it2].x), f2tf32(rx[it2].y),
                             f2tf32(rx[it2].z), f2tf32(rx[it2].w));
        *(uint4*)&xs[r * 36 + c4] = v;
    }
    #pragma unroll
    for (int it2 = 0; it2 < 6; it2++) {
        int e = t + it2 * 256, r = e >> 3, c4 = (e & 7) * 4;
        *(uint4*)&ws[r * 36 + c4] = rw[it2];
    }
    __syncthreads();

    int buf = 0;
    for (int it = 0; it < 32; it++) {
        if (it < 31) {
            int k0 = (it + 1) * 32;
            #pragma unroll
            for (int it2 = 0; it2 < 2; it2++) {
                int e = t + it2 * 256, r = e >> 3, c4 = (e & 7) * 4;
                rx[it2] = *(const float4*)&x[(size_t)(row0 + r) * NC + k0 + c4];
            }
            #pragma unroll
            for (int it2 = 0; it2 < 6; it2++) {
                int e = t + it2 * 256, r = e >> 3, c4 = (e & 7) * 4;
                rw[it2] = *(const uint4*)&g_wc[(size_t)r * NC + k0 + c4];
            }
        }

        const unsigned* xb = xs + buf * (64 * 36);
        const unsigned* wb = ws + buf * (192 * 36);
        #pragma unroll
        for (int ks = 0; ks < 4; ks++) {
            int kb = ks * 8;
            unsigned a[2][4], b[6][2];
            #pragma unroll
            for (int mt = 0; mt < 2; mt++) {
                int r = wm * 32 + mt * 16 + g;
                a[mt][0] = xb[r * 36 + kb + tg];
                a[mt][1] = xb[(r + 8) * 36 + kb + tg];
                a[mt][2] = xb[r * 36 + kb + tg + 4];
                a[mt][3] = xb[(r + 8) * 36 + kb + tg + 4];
            }
            #pragma unroll
            for (int nt = 0; nt < 6; nt++) {
                int c = wn * 48 + nt * 8 + g;
                b[nt][0] = wb[c * 36 + kb + tg];
                b[nt][1] = wb[c * 36 + kb + tg + 4];
            }
            #pragma unroll
            for (int mt = 0; mt < 2; mt++)
                #pragma unroll
                for (int nt = 0; nt < 6; nt++)
                    mma_tf32(d[mt][nt], a[mt], b[nt]);
        }

        if (it < 31) {
            unsigned* xo = xs + (buf ^ 1) * (64 * 36);
            unsigned* wo = ws + (buf ^ 1) * (192 * 36);
            #pragma unroll
            for (int it2 = 0; it2 < 2; it2++) {
                int e = t + it2 * 256, r = e >> 3, c4 = (e & 7) * 4;
                uint4 v = make_uint4(f2tf32(rx[it2].x), f2tf32(rx[it2].y),
                                     f2tf32(rx[it2].z), f2tf32(rx[it2].w));
                *(uint4*)&xo[r * 36 + c4] = v;
            }
            #pragma unroll
            for (int it2 = 0; it2 < 6; it2++) {
                int e = t + it2 * 256, r = e >> 3, c4 = (e & 7) * 4;
                *(uint4*)&wo[r * 36 + c4] = rw[it2];
            }
        }
        __syncthreads();
        buf ^= 1;
    }

    #pragma unroll
    for (int mt = 0; mt < 2; mt++) {
        int r = row0 + wm * 32 + mt * 16 + g;
        #pragma unroll
        for (int nt = 0; nt < 6; nt++) {
            int c = wn * 48 + nt * 8 + tg * 2;
            int m = c >> 6, col = c & 63;
            unsigned* O = (m == 0) ? g_q : (m == 1) ? g_k : g_v;
            uint2 v0 = make_uint2(f2tf32(d[mt][nt][0]), f2tf32(d[mt][nt][1]));
            uint2 v1 = make_uint2(f2tf32(d[mt][nt][2]), f2tf32(d[mt][nt][3]));
            *(uint2*)&O[(size_t)r * NH + col]       = v0;
            *(uint2*)&O[(size_t)(r + 8) * NH + col] = v1;
        }
    }
}

// ---------------------------------------------------------------------------
// Kernel 2: causal attention, split-K.
// K single-buffered w/ XOR swizzle (P lives in registers + shuffles);
// V double-buffered. cp.async pipeline both ways; smem=53248 -> 4 blocks/SM.
// ---------------------------------------------------------------------------
__global__ __launch_bounds__(128, 4) void attn_kernel(float* __restrict__ out) {
    extern __shared__ unsigned sm[];
    unsigned* Ksm = sm;                   // 64x64 XOR-swizzled
    unsigned* Vsm = sm + 64 * 64;         // 2 x 64x72
    unsigned smem_u32 = (unsigned)__cvta_generic_to_shared(sm);
    unsigned ksm_u32 = smem_u32;
    unsigned vsm_u32 = smem_u32 + 64 * 64 * 4;

    int t = threadIdx.x, lane = t & 31, w = t >> 5;
    int g = lane >> 2, tg = lane & 3;
    int b = blockIdx.y;
    const unsigned FULL = 0xffffffffu;

    // decode (q-tile i, chunk); heavy pairs first
    int p = NPAIR - 1 - blockIdx.x;
    int i = 0, nch = 1;
    while (p >= nch) { p -= nch; i++; nch = (i >> 3) + 1; }
    int chunk = p;
    int q0 = i * 64;
    int kt0 = chunk * 8;
    int kt1 = min(kt0 + 8, i + 1);
    int ntiles = kt1 - kt0;

    // prologue: K(kt0) + V(kt0)->buf0
    {
        const unsigned* kg = g_k + (size_t)(b * NT + kt0 * 64) * NH;
        const unsigned* vg = g_v + (size_t)(b * NT + kt0 * 64) * NH;
        #pragma unroll
        for (int it = 0; it < 8; it++) {
            int e = t + it * 128, r = e >> 4, c4 = (e & 15) * 4;
            cp16(ksm_u32 + (r * 64 + (c4 ^ (4 * (r & 7)))) * 4, kg + r * NH + c4);
            cp16(vsm_u32 + (r * 72 + c4) * 4, vg + r * NH + c4);
        }
        CP_COMMIT();
    }

    // Q fragments (register-resident)
    unsigned qa[8][4];
    {
        const unsigned* qg = g_q + (size_t)(b * NT + q0) * NH;
        int r = w * 16 + g;
        #pragma unroll
        for (int ks = 0; ks < 8; ks++) {
            int kb = ks * 8;
            qa[ks][0] = qg[r * NH + kb + tg];
            qa[ks][1] = qg[(r + 8) * NH + kb + tg];
            qa[ks][2] = qg[r * NH + kb + tg + 4];
            qa[ks][3] = qg[(r + 8) * NH + kb + tg + 4];
        }
    }

    float o[8][4];
    #pragma unroll
    for (int nt = 0; nt < 8; nt++)
        #pragma unroll
        for (int c = 0; c < 4; c++) o[nt][c] = 0.f;
    float rs0 = 0.f, rs1 = 0.f;

    int srcA = (lane & ~3) | (tg >> 1);   // P-shuffle source lanes
    int srcB = srcA + 2;
    bool oddc = tg & 1;

    for (int n = 0; n < ntiles; n++) {
        int kt = kt0 + n;
        int s0 = kt * 64;
        int buf = n & 1;
        unsigned* Vb = Vsm + buf * (64 * 72);

        CP_WAIT0();        // K(n) [+ V(n)] arrived
        __syncthreads();   // visibility + prev-iter consumers done

        if (n + 1 < ntiles) {   // prefetch V(n+1) -> buf^1 (covered by S+exp)
            const unsigned* vg = g_v + (size_t)(b * NT + s0 + 64) * NH;
            unsigned vd = vsm_u32 + (buf ^ 1) * (64 * 72 * 4);
            #pragma unroll
            for (int it = 0; it < 8; it++) {
                int e = t + it * 128, r = e >> 4, c4 = (e & 15) * 4;
                cp16(vd + (r * 72 + c4) * 4, vg + r * NH + c4);
            }
            CP_COMMIT();
        }

        bool diag = (kt == i);
        int lim = diag ? (w * 16 + 15) : 1000000;

        // S = Q K^T  (K XOR-swizzled: col ^ 4*(row&7); row&7 == g here)
        float s[8][4];
        #pragma unroll
        for (int nt = 0; nt < 8; nt++)
            #pragma unroll
            for (int c = 0; c < 4; c++) s[nt][c] = 0.f;
        int swz = 4 * g;
        #pragma unroll
        for (int ks = 0; ks < 8; ks++) {
            int kb = ks * 8;
            #pragma unroll
            for (int nt = 0; nt < 8; nt++) {
                if (nt * 8 <= lim) {
                    unsigned bf[2];
                    int c = nt * 8 + g;
                    bf[0] = Ksm[c * 64 + ((kb + tg)     ^ swz)];
                    bf[1] = Ksm[c * 64 + ((kb + tg + 4) ^ swz)];
                    mma_tf32(s[nt], qa[ks], bf);
                }
            }
        }
        __syncthreads();   // all warps done reading K

        if (n + 1 < ntiles) {   // prefetch K(n+1) (covered by exp + PV)
            const unsigned* kg = g_k + (size_t)(b * NT + s0 + 64) * NH;
            #pragma unroll
            for (int it = 0; it < 8; it++) {
                int e = t + it * 128, r = e >> 4, c4 = (e & 15) * 4;
                cp16(ksm_u32 + (r * 64 + (c4 ^ (4 * (r & 7)))) * 4,
                     kg + r * NH + c4);
            }
            CP_COMMIT();
        }

        // exp + causal mask + row sums
        int qi0 = q0 + w * 16 + g;
        float p0 = 0.f, p1 = 0.f;
        #pragma unroll
        for (int nt = 0; nt < 8; nt++) {
            int c0 = s0 + nt * 8 + tg * 2;
            float e0 = __expf(s[nt][0] * 0.125f);
            float e1 = __expf(s[nt][1] * 0.125f);
            float e2 = __expf(s[nt][2] * 0.125f);
            float e3 = __expf(s[nt][3] * 0.125f);
            if (diag) {
                if (c0 > qi0)         e0 = 0.f;
                if (c0 + 1 > qi0)     e1 = 0.f;
                if (c0 > qi0 + 8)     e2 = 0.f;
                if (c0 + 1 > qi0 + 8) e3 = 0.f;
            }
            s[nt][0] = e0; s[nt][1] = e1; s[nt][2] = e2; s[nt][3] = e3;
            p0 += e0 + e1; p1 += e2 + e3;
        }
        p0 += __shfl_xor_sync(FULL, p0, 1);
        p0 += __shfl_xor_sync(FULL, p0, 2);
        p1 += __shfl_xor_sync(FULL, p1, 1);
        p1 += __shfl_xor_sync(FULL, p1, 2);
        rs0 += p0; rs1 += p1;

        // O += P V   (P A-fragments gathered via shuffles — no smem)
        #pragma unroll
        for (int ks = 0; ks < 8; ks++) {
            if (ks * 8 <= lim) {
                float a0 = __shfl_sync(FULL, s[ks][0], srcA);
                float a1 = __shfl_sync(FULL, s[ks][1], srcA);
                float a2 = __shfl_sync(FULL, s[ks][2], srcA);
                float a3 = __shfl_sync(FULL, s[ks][3], srcA);
                float b0 = __shfl_sync(FULL, s[ks][0], srcB);
                float b1 = __shfl_sync(FULL, s[ks][1], srcB);
                float b2 = __shfl_sync(FULL, s[ks][2], srcB);
                float b3 = __shfl_sync(FULL, s[ks][3], srcB);
                unsigned pa[4];
                pa[0] = f2tf32(oddc ? a1 : a0);
                pa[1] = f2tf32(oddc ? a3 : a2);
                pa[2] = f2tf32(oddc ? b1 : b0);
                pa[3] = f2tf32(oddc ? b3 : b2);
                int kb = ks * 8;
                #pragma unroll
                for (int nt = 0; nt < 8; nt++) {
                    unsigned bf[2];
                    int nn = nt * 8 + g;
                    bf[0] = Vb[(kb + tg) * 72 + nn];
                    bf[1] = Vb[(kb + tg + 4) * 72 + nn];
                    mma_tf32(o[nt], pa, bf);
                }
            }
        }
    }

    int rbase = b * NT + q0 + w * 16 + g;
    if (nch == 1) {
        float inv0 = 1.f / rs0, inv1 = 1.f / rs1;
        #pragma unroll
        for (int nt = 0; nt < 8; nt++) {
            int c = nt * 8 + tg * 2;
            *(float2*)&out[(size_t)rbase * NH + c] =
                make_float2(o[nt][0] * inv0, o[nt][1] * inv0);
            *(float2*)&out[(size_t)(rbase + 8) * NH + c] =
                make_float2(o[nt][2] * inv1, o[nt][3] * inv1);
        }
    } else {
        float* po = g_po[chunk];
        #pragma unroll
        for (int nt = 0; nt < 8; nt++) {
            int c = nt * 8 + tg * 2;
            *(float2*)&po[(size_t)rbase * NH + c]       = make_float2(o[nt][0], o[nt][1]);
            *(float2*)&po[(size_t)(rbase + 8) * NH + c] = make_float2(o[nt][2], o[nt][3]);
        }
        if (tg == 0) {
            g_prs[chunk][rbase]     = rs0;
            g_prs[chunk][rbase + 8] = rs1;
        }
    }
}

// ---------------------------------------------------------------------------
// Kernel 3: combine split-K partials (tail rows only: q-tile i >= 8), float4.
// ---------------------------------------------------------------------------
__global__ __launch_bounds__(256) void reduce_kernel(float* __restrict__ out) {
    int f4 = blockIdx.x * 256 + threadIdx.x;   // 0..196607
    int rr = f4 >> 4;                          // tail-row id
    int bb = rr / 1536;
    int rl = rr - bb * 1536;
    int r  = bb * NT + 512 + rl;
    int i  = (512 + rl) >> 6;
    int nch = (i >> 3) + 1;                    // 2..4
    int c4 = (f4 & 15) * 4;
    size_t off = (size_t)r * NH + c4;
    float4 num = *(const float4*)&g_po[0][off];
    float  den = g_prs[0][r];
    for (int c = 1; c < nch; c++) {
        float4 q = *(const float4*)&g_po[c][off];
        num.x += q.x; num.y += q.y; num.z += q.z; num.w += q.w;
        den += g_prs[c][r];
    }
    float inv = 1.f / den;
    *(float4*)&out[off] = make_float4(num.x * inv, num.y * inv,
                                      num.z * inv, num.w * inv);
}

extern "C" void kernel_launch(void* const* d_in, const int* in_sizes, int n_in,
                              void* d_out, int out_size) {
    const float* x  = (const float*)d_in[0];
    const float* Wk = (const float*)d_in[1];
    const float* Wq = (const float*)d_in[2];
    const float* Wv = (const float*)d_in[3];
    float* out = (float*)d_out;

    const int proj_smem = (2 * 64 * 36 + 2 * 192 * 36) * 4;   // 73728 B
    const int attn_smem = (64 * 64 + 2 * 64 * 72) * 4;        // 53248 B
    (void)cudaFuncSetAttribute(proj_kernel,
                               cudaFuncAttributeMaxDynamicSharedMemorySize,
                               proj_smem);
    (void)cudaFuncSetAttribute(attn_kernel,
                               cudaFuncAttributeMaxDynamicSharedMemorySize,
                               attn_smem);

    wcvt_kernel<<<192 * NC / 256, 256>>>(Wq, Wk, Wv);
    proj_kernel<<<BT / 64, 256, proj_smem>>>(x);
    attn_kernel<<<dim3(NPAIR, NB), 128, attn_smem>>>(out);
    reduce_kernel<<<768, 256>>>(out);
}